// round 4
// baseline (speedup 1.0000x reference)
#include <cuda_runtime.h>

// Problem constants (fixed by the dataset)
#define BQ 32          // batch
#define HKV 8          // kv heads
#define G 4            // gqa group size (32/8)
#define D 128          // head dim
#define PS 16          // page size
#define PAGES_PER_SEQ 256
#define CHUNKS 8
#define CHUNK_PAGES (PAGES_PER_SEQ / CHUNKS)   // 32
#define CHUNK_TOKENS (CHUNK_PAGES * PS)        // 512

// Split-KV partial scratch: [B][HKV][CHUNKS][G]
__device__ float g_pl[BQ * HKV * CHUNKS * G];
__device__ float g_pa[BQ * HKV * CHUNKS * G * D];
__device__ int   g_cnt[BQ * HKV];   // zero-initialized; reset by merging CTA each launch

__device__ __forceinline__ float4 ldcs4(const float* p) {
    return __ldcs(reinterpret_cast<const float4*>(p));
}
__device__ __forceinline__ float4 ldcg4(const float* p) {
    return __ldcg(reinterpret_cast<const float4*>(p));
}

union f2u { float2 f; unsigned long long u; };

// packed 2xfp32 fma (Blackwell f32x2 pipe) — halves FMA-pipe issue count
__device__ __forceinline__ float2 ffma2(float2 a, float2 b, float2 c) {
    f2u A, B, C, Dd; A.f = a; B.f = b; C.f = c;
    asm("fma.rn.f32x2 %0, %1, %2, %3;" : "=l"(Dd.u) : "l"(A.u), "l"(B.u), "l"(C.u));
    return Dd.f;
}
__device__ __forceinline__ float2 fadd2(float2 a, float2 b) {
    f2u A, B, Dd; A.f = a; B.f = b;
    asm("add.rn.f32x2 %0, %1, %2;" : "=l"(Dd.u) : "l"(A.u), "l"(B.u));
    return Dd.f;
}

struct AttState {
    float2 q_lo[G], q_hi[G];      // prescaled q, this lane's 4 dims
    float2 acc_lo[G], acc_hi[G];  // V accumulators
    float2 l01, l23;              // sum of weights, heads 0/1 and 2/3
};

// process one token given its K/V float4 for this lane's dims
__device__ __forceinline__ void proc_token(AttState& st, float4 k4, float4 v4) {
    const float2 klo = make_float2(k4.x, k4.y), khi = make_float2(k4.z, k4.w);
    const float2 vlo = make_float2(v4.x, v4.y), vhi = make_float2(v4.z, v4.w);
    float s[G];
#pragma unroll
    for (int g = 0; g < G; g++) {
        float2 d2 = ffma2(st.q_lo[g], klo, make_float2(0.f, 0.f));
        d2 = ffma2(st.q_hi[g], khi, d2);
        s[g] = d2.x + d2.y;
    }
#pragma unroll
    for (int off = 16; off; off >>= 1) {
#pragma unroll
        for (int g = 0; g < G; g++)
            s[g] += __shfl_xor_sync(0xffffffffu, s[g], off);
    }
    float p[G];
#pragma unroll
    for (int g = 0; g < G; g++) p[g] = exp2f(s[g]);   // q prescaled by scale*log2e
    st.l01 = fadd2(st.l01, make_float2(p[0], p[1]));
    st.l23 = fadd2(st.l23, make_float2(p[2], p[3]));
#pragma unroll
    for (int g = 0; g < G; g++) {
        const float2 p2 = make_float2(p[g], p[g]);
        st.acc_lo[g] = ffma2(p2, vlo, st.acc_lo[g]);
        st.acc_hi[g] = ffma2(p2, vhi, st.acc_hi[g]);
    }
}

__global__ __launch_bounds__(128, 5)
void attn_fused(const float* __restrict__ q,
                const float* __restrict__ kvc,
                const int* __restrict__ indptr,
                const int* __restrict__ indices,
                const int* __restrict__ lastlen,
                float* __restrict__ out)
{
    const int chunk = blockIdx.x;
    const int h     = blockIdx.y;
    const int b     = blockIdx.z;
    const int tid   = threadIdx.x;
    const int w     = tid >> 5;
    const int lane  = tid & 31;

    __shared__ float qs[G][D];
    __shared__ int   pages[CHUNK_PAGES];
    __shared__ float sm_l[4][G];
    __shared__ float sm_acc[4][G][D];
    __shared__ int   sm_arrive;

    const int p0     = indptr[b];
    const int npages = indptr[b + 1] - p0;
    const int valid_len = (npages - 1) * PS + lastlen[b];

    // stage q (pre-scaled by 1/sqrt(D) * log2(e) so softmax uses exp2)
    const float scale = 0.08838834764831845f * 1.4426950408889634f;
    for (int i = tid; i < G * D; i += 128) {
        int g = i >> 7, d = i & (D - 1);
        qs[g][d] = q[((size_t)(b * HKV * G) + h * G + g) * D + d] * scale;
    }
    if (tid < CHUNK_PAGES) {
        int pg = chunk * CHUNK_PAGES + tid;
        pages[tid] = (pg < npages) ? indices[p0 + pg] : 0;
    }
    __syncthreads();

    const int lane4 = lane * 4;

    AttState st;
#pragma unroll
    for (int g = 0; g < G; g++) {
        const float4 qv = *(const float4*)&qs[g][lane4];
        st.q_lo[g] = make_float2(qv.x, qv.y);
        st.q_hi[g] = make_float2(qv.z, qv.w);
        st.acc_lo[g] = make_float2(0.f, 0.f);
        st.acc_hi[g] = make_float2(0.f, 0.f);
    }
    st.l01 = make_float2(0.f, 0.f);
    st.l23 = make_float2(0.f, 0.f);

    const int tok0 = chunk * CHUNK_TOKENS;
    int tmax = valid_len - tok0;
    if (tmax > CHUNK_TOKENS) tmax = CHUNK_TOKENS;

    const size_t v_off = (size_t)HKV * PS * D;   // in floats
    const int full_pages = tmax >> 4;            // complete pages in this chunk

    // fast path: full pages; warp w owns positions {w, w+4, w+8, w+12}
    for (int pg = 0; pg < full_pages; pg++) {
        const float* base = kvc
            + ((size_t)pages[pg] * (2 * HKV) + h) * (PS * D)
            + (size_t)w * D + lane4;
        const float4 k0 = ldcs4(base);
        const float4 k1 = ldcs4(base + 512);
        const float4 k2 = ldcs4(base + 1024);
        const float4 k3 = ldcs4(base + 1536);
        const float4 v0 = ldcs4(base + v_off);
        const float4 v1 = ldcs4(base + v_off + 512);
        const float4 v2 = ldcs4(base + v_off + 1024);
        const float4 v3 = ldcs4(base + v_off + 1536);
        proc_token(st, k0, v0);
        proc_token(st, k1, v1);
        proc_token(st, k2, v2);
        proc_token(st, k3, v3);
    }

    // tail: partial last page (only the final chunk of a sequence hits this)
    for (int t = full_pages * PS + w; t < tmax; t += 4) {
        const float* base = kvc
            + ((size_t)pages[t >> 4] * (2 * HKV) + h) * (PS * D)
            + (size_t)(t & (PS - 1)) * D + lane4;
        proc_token(st, ldcs4(base), ldcs4(base + v_off));
    }

    // publish per-warp partials (l replicated across lanes after butterfly)
    if (lane == 0) {
        sm_l[w][0] = st.l01.x; sm_l[w][1] = st.l01.y;
        sm_l[w][2] = st.l23.x; sm_l[w][3] = st.l23.y;
    }
#pragma unroll
    for (int g = 0; g < G; g++) {
        float4 a = make_float4(st.acc_lo[g].x, st.acc_lo[g].y,
                               st.acc_hi[g].x, st.acc_hi[g].y);
        *(float4*)&sm_acc[w][g][lane4] = a;
    }
    __syncthreads();

    // intra-CTA merge; thread -> (g = tid>>5, dims 4*(tid&31))
    const int cg  = tid >> 5;
    const int cln = tid & 31;
    {
        float L = 0.f;
        float4 a = make_float4(0.f, 0.f, 0.f, 0.f);
#pragma unroll
        for (int wi = 0; wi < 4; wi++) {
            L += sm_l[wi][cg];
            const float4 av = *(const float4*)&sm_acc[wi][cg][cln * 4];
            a.x += av.x; a.y += av.y; a.z += av.z; a.w += av.w;
        }
        const size_t pidx = (((size_t)(b * HKV + h) * CHUNKS + chunk) * G + cg);
        if (cln == 0) g_pl[pidx] = L;
        *(float4*)&g_pa[pidx * D + cln * 4] = a;
    }

    // ---- last-CTA-per-(b,h) merges the 8 chunk partials ----
    __threadfence();
    if (tid == 0)
        sm_arrive = atomicAdd(&g_cnt[b * HKV + h], 1);
    __syncthreads();
    if (sm_arrive != CHUNKS - 1) return;
    __threadfence();   // acquire side: order partial reads after the counter obs.

    const size_t base = ((size_t)(b * HKV + h) * CHUNKS) * G + cg;
    float L = 0.f;
    float4 a = make_float4(0.f, 0.f, 0.f, 0.f);
#pragma unroll
    for (int c = 0; c < CHUNKS; c++) {
        const size_t pidx = base + (size_t)c * G;
        L += __ldcg(&g_pl[pidx]);
        const float4 av = ldcg4(&g_pa[pidx * D + cln * 4]);
        a.x += av.x; a.y += av.y; a.z += av.z; a.w += av.w;
    }
    const float inv = 1.f / L;
    float4 o = make_float4(a.x * inv, a.y * inv, a.z * inv, a.w * inv);
    *(float4*)&out[((size_t)(b * HKV * G) + h * G + cg) * D + cln * 4] = o;

    // reset counter for the next graph replay (only this CTA touches it now)
    if (tid == 0) g_cnt[b * HKV + h] = 0;
}

extern "C" void kernel_launch(void* const* d_in, const int* in_sizes, int n_in,
                              void* d_out, int out_size)
{
    const float* q       = (const float*)d_in[0];
    const float* kvc     = (const float*)d_in[1];
    const int*   indptr  = (const int*)d_in[2];
    const int*   indices = (const int*)d_in[3];
    const int*   lastlen = (const int*)d_in[4];
    float* out = (float*)d_out;

    dim3 g1(CHUNKS, HKV, BQ);
    attn_fused<<<g1, 128>>>(q, kvc, indptr, indices, lastlen, out);
}

// round 5
// speedup vs baseline: 1.0572x; 1.0572x over previous
#include <cuda_runtime.h>

// Problem constants (fixed by the dataset)
#define BQ 32          // batch
#define HKV 8          // kv heads
#define G 4            // gqa group size (32/8)
#define D 128          // head dim
#define PS 16          // page size
#define PAGES_PER_SEQ 256
#define CHUNKS 16
#define CHUNK_PAGES (PAGES_PER_SEQ / CHUNKS)   // 16
#define CHUNK_TOKENS (CHUNK_PAGES * PS)        // 256

// Split-KV partial scratch: [B][HKV][CHUNKS][G]
__device__ float g_pl[BQ * HKV * CHUNKS * G];
__device__ float g_pa[BQ * HKV * CHUNKS * G * D];
__device__ int   g_cnt[BQ * HKV];   // zero-init; reset by merging CTA each launch

__device__ __forceinline__ float4 ldcs4(const float* p) {
    return __ldcs(reinterpret_cast<const float4*>(p));
}
__device__ __forceinline__ float4 ldcg4(const float* p) {
    return __ldcg(reinterpret_cast<const float4*>(p));
}

union f2u { float2 f; unsigned long long u; };

// packed 2xfp32 fma (Blackwell f32x2 pipe)
__device__ __forceinline__ float2 ffma2(float2 a, float2 b, float2 c) {
    f2u A, B, C, Dd; A.f = a; B.f = b; C.f = c;
    asm("fma.rn.f32x2 %0, %1, %2, %3;" : "=l"(Dd.u) : "l"(A.u), "l"(B.u), "l"(C.u));
    return Dd.f;
}
__device__ __forceinline__ float2 fadd2(float2 a, float2 b) {
    f2u A, B, Dd; A.f = a; B.f = b;
    asm("add.rn.f32x2 %0, %1, %2;" : "=l"(Dd.u) : "l"(A.u), "l"(B.u));
    return Dd.f;
}

struct AttState {
    float2 q_lo[G], q_hi[G];      // prescaled q, this lane's 4 dims
    float2 acc_lo[G], acc_hi[G];  // V accumulators
    float2 l01, l23;              // weight sums, heads 0/1 and 2/3
};

__device__ __forceinline__ void proc_token(AttState& st, float4 k4, float4 v4) {
    const float2 klo = make_float2(k4.x, k4.y), khi = make_float2(k4.z, k4.w);
    const float2 vlo = make_float2(v4.x, v4.y), vhi = make_float2(v4.z, v4.w);
    float s[G];
#pragma unroll
    for (int g = 0; g < G; g++) {
        float2 d2 = ffma2(st.q_lo[g], klo, make_float2(0.f, 0.f));
        d2 = ffma2(st.q_hi[g], khi, d2);
        s[g] = d2.x + d2.y;
    }
#pragma unroll
    for (int off = 16; off; off >>= 1) {
#pragma unroll
        for (int g = 0; g < G; g++)
            s[g] += __shfl_xor_sync(0xffffffffu, s[g], off);
    }
    float p[G];
#pragma unroll
    for (int g = 0; g < G; g++) p[g] = exp2f(s[g]);   // q prescaled by scale*log2e
    st.l01 = fadd2(st.l01, make_float2(p[0], p[1]));
    st.l23 = fadd2(st.l23, make_float2(p[2], p[3]));
#pragma unroll
    for (int g = 0; g < G; g++) {
        const float2 p2 = make_float2(p[g], p[g]);
        st.acc_lo[g] = ffma2(p2, vlo, st.acc_lo[g]);
        st.acc_hi[g] = ffma2(p2, vhi, st.acc_hi[g]);
    }
}

__global__ __launch_bounds__(128, 4)
void attn_fused(const float* __restrict__ q,
                const float* __restrict__ kvc,
                const int* __restrict__ indptr,
                const int* __restrict__ indices,
                const int* __restrict__ lastlen,
                float* __restrict__ out)
{
    const int chunk = blockIdx.x;
    const int h     = blockIdx.y;
    const int b     = blockIdx.z;
    const int tid   = threadIdx.x;
    const int w     = tid >> 5;
    const int lane  = tid & 31;

    __shared__ float qs[G][D];
    __shared__ int   pages[CHUNK_PAGES];
    __shared__ float sm_l[4][G];
    __shared__ float sm_acc[4][G][D];
    __shared__ int   sm_arrive;

    const int p0     = indptr[b];
    const int npages = indptr[b + 1] - p0;
    const int valid_len = (npages - 1) * PS + lastlen[b];

    // stage q (pre-scaled by 1/sqrt(D) * log2(e) so softmax uses exp2)
    const float scale = 0.08838834764831845f * 1.4426950408889634f;
    for (int i = tid; i < G * D; i += 128) {
        int g = i >> 7, d = i & (D - 1);
        qs[g][d] = q[((size_t)(b * HKV * G) + h * G + g) * D + d] * scale;
    }
    if (tid < CHUNK_PAGES) {
        int pg = chunk * CHUNK_PAGES + tid;
        pages[tid] = (pg < npages) ? indices[p0 + pg] : 0;
    }
    __syncthreads();

    const int lane4 = lane * 4;

    AttState st;
#pragma unroll
    for (int g = 0; g < G; g++) {
        const float4 qv = *(const float4*)&qs[g][lane4];
        st.q_lo[g] = make_float2(qv.x, qv.y);
        st.q_hi[g] = make_float2(qv.z, qv.w);
        st.acc_lo[g] = make_float2(0.f, 0.f);
        st.acc_hi[g] = make_float2(0.f, 0.f);
    }
    st.l01 = make_float2(0.f, 0.f);
    st.l23 = make_float2(0.f, 0.f);

    const int tok0 = chunk * CHUNK_TOKENS;
    int tmax = valid_len - tok0;
    if (tmax > CHUNK_TOKENS) tmax = CHUNK_TOKENS;

    const size_t v_off = (size_t)HKV * PS * D;   // in floats
    const int full_pages = tmax >> 4;            // >= 15 for this problem shape

    const size_t wl = (size_t)w * D + lane4;

    // ---- double-buffered page loop: prefetch pg+1 before processing pg ----
    float4 kb[4], vb[4];
    {
        const float* bp = kvc + ((size_t)pages[0] * (2 * HKV) + h) * (PS * D) + wl;
#pragma unroll
        for (int i = 0; i < 4; i++) {
            kb[i] = ldcs4(bp + i * 512);
            vb[i] = ldcs4(bp + v_off + i * 512);
        }
    }
    for (int pg = 0; pg + 1 < full_pages; pg++) {
        float4 kn[4], vn[4];
        const float* np = kvc + ((size_t)pages[pg + 1] * (2 * HKV) + h) * (PS * D) + wl;
#pragma unroll
        for (int i = 0; i < 4; i++) {
            kn[i] = ldcs4(np + i * 512);
            vn[i] = ldcs4(np + v_off + i * 512);
        }
#pragma unroll
        for (int i = 0; i < 4; i++)
            proc_token(st, kb[i], vb[i]);
#pragma unroll
        for (int i = 0; i < 4; i++) { kb[i] = kn[i]; vb[i] = vn[i]; }
    }
#pragma unroll
    for (int i = 0; i < 4; i++)          // last full page
        proc_token(st, kb[i], vb[i]);

    // tail: partial last page (only the final chunk of a sequence hits this)
    for (int t = full_pages * PS + w; t < tmax; t += 4) {
        const float* base = kvc
            + ((size_t)pages[t >> 4] * (2 * HKV) + h) * (PS * D)
            + (size_t)(t & (PS - 1)) * D + lane4;
        proc_token(st, ldcs4(base), ldcs4(base + v_off));
    }

    // publish per-warp partials (l replicated across lanes after butterfly)
    if (lane == 0) {
        sm_l[w][0] = st.l01.x; sm_l[w][1] = st.l01.y;
        sm_l[w][2] = st.l23.x; sm_l[w][3] = st.l23.y;
    }
#pragma unroll
    for (int g = 0; g < G; g++) {
        float4 a = make_float4(st.acc_lo[g].x, st.acc_lo[g].y,
                               st.acc_hi[g].x, st.acc_hi[g].y);
        *(float4*)&sm_acc[w][g][lane4] = a;
    }
    __syncthreads();

    // intra-CTA merge; thread -> (g = tid>>5, dims 4*(tid&31))
    const int cg  = tid >> 5;
    const int cln = tid & 31;
    {
        float L = 0.f;
        float4 a = make_float4(0.f, 0.f, 0.f, 0.f);
#pragma unroll
        for (int wi = 0; wi < 4; wi++) {
            L += sm_l[wi][cg];
            const float4 av = *(const float4*)&sm_acc[wi][cg][cln * 4];
            a.x += av.x; a.y += av.y; a.z += av.z; a.w += av.w;
        }
        const size_t pidx = (((size_t)(b * HKV + h) * CHUNKS + chunk) * G + cg);
        if (cln == 0) g_pl[pidx] = L;
        *(float4*)&g_pa[pidx * D + cln * 4] = a;
    }

    // ---- last-CTA-per-(b,h) merges the CHUNKS chunk partials ----
    __threadfence();
    if (tid == 0)
        sm_arrive = atomicAdd(&g_cnt[b * HKV + h], 1);
    __syncthreads();
    if (sm_arrive != CHUNKS - 1) return;
    __threadfence();   // order partial reads after the counter observation

    const size_t base = ((size_t)(b * HKV + h) * CHUNKS) * G + cg;
    float L = 0.f;
    float4 a = make_float4(0.f, 0.f, 0.f, 0.f);
#pragma unroll
    for (int c = 0; c < CHUNKS; c++) {
        const size_t pidx = base + (size_t)c * G;
        L += __ldcg(&g_pl[pidx]);
        const float4 av = ldcg4(&g_pa[pidx * D + cln * 4]);
        a.x += av.x; a.y += av.y; a.z += av.z; a.w += av.w;
    }
    const float inv = 1.f / L;
    float4 o = make_float4(a.x * inv, a.y * inv, a.z * inv, a.w * inv);
    *(float4*)&out[((size_t)(b * HKV * G) + h * G + cg) * D + cln * 4] = o;

    // reset counter for the next graph replay (only this CTA touches it)
    if (tid == 0) g_cnt[b * HKV + h] = 0;
}

extern "C" void kernel_launch(void* const* d_in, const int* in_sizes, int n_in,
                              void* d_out, int out_size)
{
    const float* q       = (const float*)d_in[0];
    const float* kvc     = (const float*)d_in[1];
    const int*   indptr  = (const int*)d_in[2];
    const int*   indices = (const int*)d_in[3];
    const int*   lastlen = (const int*)d_in[4];
    float* out = (float*)d_out;

    dim3 g1(CHUNKS, HKV, BQ);
    attn_fused<<<g1, 128>>>(q, kvc, indptr, indices, lastlen, out);
}

// round 7
// speedup vs baseline: 1.0811x; 1.0225x over previous
#include <cuda_runtime.h>

// Problem constants (fixed by the dataset)
#define BQ 32          // batch
#define HKV 8          // kv heads
#define G 4            // gqa group size (32/8)
#define D 128          // head dim
#define PS 16          // page size
#define PAGES_PER_SEQ 256
#define CHUNKS 16
#define CHUNK_PAGES (PAGES_PER_SEQ / CHUNKS)   // 16
#define CHUNK_TOKENS (CHUNK_PAGES * PS)        // 256

// Split-KV partial scratch: [B][HKV][CHUNKS][G]
__device__ float g_pl[BQ * HKV * CHUNKS * G];
__device__ float g_pa[BQ * HKV * CHUNKS * G * D];
__device__ int   g_cnt[BQ * HKV];   // zero-init; reset by merging CTA each launch

__device__ __forceinline__ float4 ldcs4(const float* p) {
    return __ldcs(reinterpret_cast<const float4*>(p));
}
__device__ __forceinline__ float4 ldcg4(const float* p) {
    return __ldcg(reinterpret_cast<const float4*>(p));
}

union f2u { float2 f; unsigned long long u; };

// packed 2xfp32 fma (Blackwell f32x2 pipe)
__device__ __forceinline__ float2 ffma2(float2 a, float2 b, float2 c) {
    f2u A, B, C, Dd; A.f = a; B.f = b; C.f = c;
    asm("fma.rn.f32x2 %0, %1, %2, %3;" : "=l"(Dd.u) : "l"(A.u), "l"(B.u), "l"(C.u));
    return Dd.f;
}

// 2-bit reverse: head permutation used by the folded reduction
__device__ __forceinline__ int perm2(int x) { return ((x & 1) << 1) | ((x >> 1) & 1); }

struct AttState {
    float2 q_lo[G], q_hi[G];      // prescaled q, this lane's 4 dims
    float2 acc_lo[G], acc_hi[G];  // V accumulators, HEAD-PERMUTED: slot i = head perm2(r^i)
    float  l_own;                 // weight sum for head perm2(r), r = lane&3
};

// Folded cross-head reduction: 9 SHFL + 1 EX2 per token (vs 20 SHFL + 4 EX2).
__device__ __forceinline__ void proc_token(AttState& st, float4 k4, float4 v4,
                                           bool bit0, bool bit1) {
    const float2 klo = make_float2(k4.x, k4.y), khi = make_float2(k4.z, k4.w);
    const float2 vlo = make_float2(v4.x, v4.y), vhi = make_float2(v4.z, v4.w);
    float s[G];
#pragma unroll
    for (int g = 0; g < G; g++) {
        float2 d2 = ffma2(st.q_lo[g], klo, make_float2(0.f, 0.f));
        d2 = ffma2(st.q_hi[g], khi, d2);
        s[g] = d2.x + d2.y;
    }
    // level 1 (xor 1): even lanes keep heads {0,1}, odd lanes keep {2,3}
    const float sx = bit0 ? s[0] : s[2];
    const float sy = bit0 ? s[1] : s[3];
    const float x = (bit0 ? s[2] : s[0]) + __shfl_xor_sync(0xffffffffu, sx, 1);
    const float y = (bit0 ? s[3] : s[1]) + __shfl_xor_sync(0xffffffffu, sy, 1);
    // level 2 (xor 2): bit1=0 keeps x-head, bit1=1 keeps y-head
    const float sz = bit1 ? x : y;
    float z = (bit1 ? y : x) + __shfl_xor_sync(0xffffffffu, sz, 2);
    // levels 3-5: plain butterfly; z = warp sum for head perm2(lane&3)
    z += __shfl_xor_sync(0xffffffffu, z, 4);
    z += __shfl_xor_sync(0xffffffffu, z, 8);
    z += __shfl_xor_sync(0xffffffffu, z, 16);

    const float p0 = exp2f(z);           // q prescaled by scale*log2e
    st.l_own += p0;
    const float p1 = __shfl_xor_sync(0xffffffffu, p0, 1);
    const float p2 = __shfl_xor_sync(0xffffffffu, p0, 2);
    const float p3 = __shfl_xor_sync(0xffffffffu, p0, 3);

    const float pp[G] = {p0, p1, p2, p3};
#pragma unroll
    for (int i = 0; i < G; i++) {
        const float2 pi = make_float2(pp[i], pp[i]);
        st.acc_lo[i] = ffma2(pi, vlo, st.acc_lo[i]);
        st.acc_hi[i] = ffma2(pi, vhi, st.acc_hi[i]);
    }
}

__global__ __launch_bounds__(128, 4)
void attn_fused(const float* __restrict__ q,
                const float* __restrict__ kvc,
                const int* __restrict__ indptr,
                const int* __restrict__ indices,
                const int* __restrict__ lastlen,
                float* __restrict__ out)
{
    const int chunk = blockIdx.x;
    const int h     = blockIdx.y;
    const int b     = blockIdx.z;
    const int tid   = threadIdx.x;
    const int w     = tid >> 5;
    const int lane  = tid & 31;
    const bool bit0 = (lane & 1) != 0;
    const bool bit1 = (lane & 2) != 0;

    __shared__ float qs[G][D];
    __shared__ int   pages[CHUNK_PAGES];
    __shared__ float sm_l[4][G];
    __shared__ float sm_acc[4][G][D];
    __shared__ int   sm_arrive;

    const int p0     = indptr[b];
    const int npages = indptr[b + 1] - p0;
    const int valid_len = (npages - 1) * PS + lastlen[b];

    // stage q (pre-scaled by 1/sqrt(D) * log2(e) so softmax uses exp2)
    const float scale = 0.08838834764831845f * 1.4426950408889634f;
    for (int i = tid; i < G * D; i += 128) {
        int g = i >> 7, d = i & (D - 1);
        qs[g][d] = q[((size_t)(b * HKV * G) + h * G + g) * D + d] * scale;
    }
    if (tid < CHUNK_PAGES) {
        int pg = chunk * CHUNK_PAGES + tid;
        pages[tid] = (pg < npages) ? indices[p0 + pg] : 0;
    }
    __syncthreads();

    const int lane4 = lane * 4;

    AttState st;
#pragma unroll
    for (int g = 0; g < G; g++) {
        const float4 qv = *(const float4*)&qs[g][lane4];
        st.q_lo[g] = make_float2(qv.x, qv.y);
        st.q_hi[g] = make_float2(qv.z, qv.w);
        st.acc_lo[g] = make_float2(0.f, 0.f);
        st.acc_hi[g] = make_float2(0.f, 0.f);
    }
    st.l_own = 0.f;

    const int tok0 = chunk * CHUNK_TOKENS;
    int tmax = valid_len - tok0;
    if (tmax > CHUNK_TOKENS) tmax = CHUNK_TOKENS;

    const size_t v_off = (size_t)HKV * PS * D;   // in floats
    const int full_pages = tmax >> 4;            // >= 15 for this problem shape

    const size_t wl = (size_t)w * D + lane4;

    // ---- double-buffered page loop: prefetch pg+1 before processing pg ----
    float4 kb[4], vb[4];
    {
        const float* bp = kvc + ((size_t)pages[0] * (2 * HKV) + h) * (PS * D) + wl;
#pragma unroll
        for (int i = 0; i < 4; i++) {
            kb[i] = ldcs4(bp + i * 512);
            vb[i] = ldcs4(bp + v_off + i * 512);
        }
    }
    for (int pg = 0; pg + 1 < full_pages; pg++) {
        float4 kn[4], vn[4];
        const float* np = kvc + ((size_t)pages[pg + 1] * (2 * HKV) + h) * (PS * D) + wl;
#pragma unroll
        for (int i = 0; i < 4; i++) {
            kn[i] = ldcs4(np + i * 512);
            vn[i] = ldcs4(np + v_off + i * 512);
        }
#pragma unroll
        for (int i = 0; i < 4; i++)
            proc_token(st, kb[i], vb[i], bit0, bit1);
#pragma unroll
        for (int i = 0; i < 4; i++) { kb[i] = kn[i]; vb[i] = vn[i]; }
    }
#pragma unroll
    for (int i = 0; i < 4; i++)          // last full page
        proc_token(st, kb[i], vb[i], bit0, bit1);

    // tail: partial last page (only the final chunk of a sequence hits this)
    for (int t = full_pages * PS + w; t < tmax; t += 4) {
        const float* base = kvc
            + ((size_t)pages[t >> 4] * (2 * HKV) + h) * (PS * D)
            + (size_t)(t & (PS - 1)) * D + lane4;
        proc_token(st, ldcs4(base), ldcs4(base + v_off), bit0, bit1);
    }

    // publish per-warp partials, un-permuting heads via computed smem addresses
    const int r = lane & 3;
    if (lane < 4) sm_l[w][perm2(lane)] = st.l_own;   // lane<4 -> r==lane
#pragma unroll
    for (int i = 0; i < G; i++) {
        const int head = perm2(r ^ i);               // head held in slot i
        float4 a = make_float4(st.acc_lo[i].x, st.acc_lo[i].y,
                               st.acc_hi[i].x, st.acc_hi[i].y);
        *(float4*)&sm_acc[w][head][lane4] = a;
    }
    __syncthreads();

    // intra-CTA merge; thread -> (g = tid>>5, dims 4*(tid&31))
    const int cg  = tid >> 5;
    const int cln = tid & 31;
    {
        float L = 0.f;
        float4 a = make_float4(0.f, 0.f, 0.f, 0.f);
#pragma unroll
        for (int wi = 0; wi < 4; wi++) {
            L += sm_l[wi][cg];
            const float4 av = *(const float4*)&sm_acc[wi][cg][cln * 4];
            a.x += av.x; a.y += av.y; a.z += av.z; a.w += av.w;
        }
        const size_t pidx = (((size_t)(b * HKV + h) * CHUNKS + chunk) * G + cg);
        if (cln == 0) g_pl[pidx] = L;
        *(float4*)&g_pa[pidx * D + cln * 4] = a;
    }

    // ---- last-CTA-per-(b,h) merges the CHUNKS chunk partials ----
    __threadfence();
    if (tid == 0)
        sm_arrive = atomicAdd(&g_cnt[b * HKV + h], 1);
    __syncthreads();
    if (sm_arrive != CHUNKS - 1) return;
    __threadfence();   // order partial reads after the counter observation

    const size_t base = ((size_t)(b * HKV + h) * CHUNKS) * G + cg;
    float L = 0.f;
    float4 a = make_float4(0.f, 0.f, 0.f, 0.f);
#pragma unroll
    for (int c = 0; c < CHUNKS; c++) {
        const size_t pidx = base + (size_t)c * G;
        L += __ldcg(&g_pl[pidx]);
        const float4 av = ldcg4(&g_pa[pidx * D + cln * 4]);
        a.x += av.x; a.y += av.y; a.z += av.z; a.w += av.w;
    }
    const float inv = 1.f / L;
    float4 o = make_float4(a.x * inv, a.y * inv, a.z * inv, a.w * inv);
    *(float4*)&out[((size_t)(b * HKV * G) + h * G + cg) * D + cln * 4] = o;

    // reset counter for the next graph replay (only this CTA touches it)
    if (tid == 0) g_cnt[b * HKV + h] = 0;
}

extern "C" void kernel_launch(void* const* d_in, const int* in_sizes, int n_in,
                              void* d_out, int out_size)
{
    const float* q       = (const float*)d_in[0];
    const float* kvc     = (const float*)d_in[1];
    const int*   indptr  = (const int*)d_in[2];
    const int*   indices = (const int*)d_in[3];
    const int*   lastlen = (const int*)d_in[4];
    float* out = (float*)d_out;

    dim3 g1(CHUNKS, HKV, BQ);
    attn_fused<<<g1, 128>>>(q, kvc, indptr, indices, lastlen, out);
}

// round 8
// speedup vs baseline: 1.1283x; 1.0437x over previous
#include <cuda_runtime.h>
#include <cstdint>

// Problem constants (fixed by the dataset)
#define BQ 32          // batch
#define HKV 8          // kv heads
#define G 4            // gqa group size (32/8)
#define D 128          // head dim
#define PS 16          // page size
#define PAGES_PER_SEQ 256
#define CHUNKS 16
#define CHUNK_PAGES (PAGES_PER_SEQ / CHUNKS)   // 16
#define CHUNK_TOKENS (CHUNK_PAGES * PS)        // 256

#define NSTAGE 2
#define PAGE_BYTES 16384       // K 8KB + V 8KB per (page, h)
#define KHALF 8192

// Split-KV partial scratch: [B][HKV][CHUNKS][G]
__device__ float g_pl[BQ * HKV * CHUNKS * G];
__device__ float g_pa[BQ * HKV * CHUNKS * G * D];
__device__ int   g_cnt[BQ * HKV];   // zero-init; reset by merging CTA each launch

__device__ __forceinline__ float4 ldcs4(const float* p) {
    return __ldcs(reinterpret_cast<const float4*>(p));
}
__device__ __forceinline__ float4 ldcg4(const float* p) {
    return __ldcg(reinterpret_cast<const float4*>(p));
}

__device__ __forceinline__ void cpasync16(uint32_t saddr, const void* gaddr) {
    asm volatile("cp.async.cg.shared.global [%0], [%1], 16;"
                 :: "r"(saddr), "l"(gaddr));
}
__device__ __forceinline__ void cp_commit() {
    asm volatile("cp.async.commit_group;" ::: "memory");
}
template <int N>
__device__ __forceinline__ void cp_wait() {
    asm volatile("cp.async.wait_group %0;" :: "n"(N) : "memory");
}

union f2u { float2 f; unsigned long long u; };

// packed 2xfp32 fma (Blackwell f32x2 pipe)
__device__ __forceinline__ float2 ffma2(float2 a, float2 b, float2 c) {
    f2u A, B, C, Dd; A.f = a; B.f = b; C.f = c;
    asm("fma.rn.f32x2 %0, %1, %2, %3;" : "=l"(Dd.u) : "l"(A.u), "l"(B.u), "l"(C.u));
    return Dd.f;
}

// 2-bit reverse: head permutation used by the folded reduction
__device__ __forceinline__ int perm2(int x) { return ((x & 1) << 1) | ((x >> 1) & 1); }

struct AttState {
    float2 q_lo[G], q_hi[G];      // prescaled q, this lane's 4 dims
    float2 acc_lo[G], acc_hi[G];  // V accumulators, HEAD-PERMUTED: slot i = head perm2(r^i)
    float  l_own;                 // weight sum for head perm2(r), r = lane&3
};

// Folded cross-head reduction: 9 SHFL + 1 EX2 per token.
__device__ __forceinline__ void proc_token(AttState& st, float4 k4, float4 v4,
                                           bool bit0, bool bit1) {
    const float2 klo = make_float2(k4.x, k4.y), khi = make_float2(k4.z, k4.w);
    const float2 vlo = make_float2(v4.x, v4.y), vhi = make_float2(v4.z, v4.w);
    float s[G];
#pragma unroll
    for (int g = 0; g < G; g++) {
        float2 d2 = ffma2(st.q_lo[g], klo, make_float2(0.f, 0.f));
        d2 = ffma2(st.q_hi[g], khi, d2);
        s[g] = d2.x + d2.y;
    }
    // level 1 (xor 1): even lanes keep heads {0,1}, odd lanes keep {2,3}
    const float sx = bit0 ? s[0] : s[2];
    const float sy = bit0 ? s[1] : s[3];
    const float x = (bit0 ? s[2] : s[0]) + __shfl_xor_sync(0xffffffffu, sx, 1);
    const float y = (bit0 ? s[3] : s[1]) + __shfl_xor_sync(0xffffffffu, sy, 1);
    // level 2 (xor 2)
    const float sz = bit1 ? x : y;
    float z = (bit1 ? y : x) + __shfl_xor_sync(0xffffffffu, sz, 2);
    // levels 3-5: plain butterfly; z = warp sum for head perm2(lane&3)
    z += __shfl_xor_sync(0xffffffffu, z, 4);
    z += __shfl_xor_sync(0xffffffffu, z, 8);
    z += __shfl_xor_sync(0xffffffffu, z, 16);

    const float p0 = exp2f(z);           // q prescaled by scale*log2e
    st.l_own += p0;
    const float p1 = __shfl_xor_sync(0xffffffffu, p0, 1);
    const float p2 = __shfl_xor_sync(0xffffffffu, p0, 2);
    const float p3 = __shfl_xor_sync(0xffffffffu, p0, 3);

    const float pp[G] = {p0, p1, p2, p3};
#pragma unroll
    for (int i = 0; i < G; i++) {
        const float2 pi = make_float2(pp[i], pp[i]);
        st.acc_lo[i] = ffma2(pi, vlo, st.acc_lo[i]);
        st.acc_hi[i] = ffma2(pi, vhi, st.acc_hi[i]);
    }
}

__global__ __launch_bounds__(128, 6)
void attn_fused(const float* __restrict__ q,
                const float* __restrict__ kvc,
                const int* __restrict__ indptr,
                const int* __restrict__ indices,
                const int* __restrict__ lastlen,
                float* __restrict__ out)
{
    const int chunk = blockIdx.x;
    const int h     = blockIdx.y;
    const int b     = blockIdx.z;
    const int tid   = threadIdx.x;
    const int w     = tid >> 5;
    const int lane  = tid & 31;
    const bool bit0 = (lane & 1) != 0;
    const bool bit1 = (lane & 2) != 0;

    // 2-stage K/V pipeline buffer; epilogue scratch aliases onto it after wait(0)
    __shared__ __align__(16) char stagebuf[NSTAGE * PAGE_BYTES];
    __shared__ float qs[G][D];
    __shared__ int   pages[CHUNK_PAGES];
    __shared__ float sm_l[4][G];
    __shared__ int   sm_arrive;

    const int p0i    = indptr[b];
    const int npages = indptr[b + 1] - p0i;
    const int valid_len = (npages - 1) * PS + lastlen[b];

    // stage q (pre-scaled by 1/sqrt(D) * log2(e) so softmax uses exp2)
    const float scale = 0.08838834764831845f * 1.4426950408889634f;
    for (int i = tid; i < G * D; i += 128) {
        int g = i >> 7, d = i & (D - 1);
        qs[g][d] = q[((size_t)(b * HKV * G) + h * G + g) * D + d] * scale;
    }
    if (tid < CHUNK_PAGES) {
        int pg = chunk * CHUNK_PAGES + tid;
        pages[tid] = (pg < npages) ? indices[p0i + pg] : 0;
    }
    __syncthreads();

    const int lane4 = lane * 4;

    AttState st;
#pragma unroll
    for (int g = 0; g < G; g++) {
        const float4 qv = *(const float4*)&qs[g][lane4];
        st.q_lo[g] = make_float2(qv.x, qv.y);
        st.q_hi[g] = make_float2(qv.z, qv.w);
        st.acc_lo[g] = make_float2(0.f, 0.f);
        st.acc_hi[g] = make_float2(0.f, 0.f);
    }
    st.l_own = 0.f;

    const int tok0 = chunk * CHUNK_TOKENS;
    int tmax = valid_len - tok0;
    if (tmax > CHUNK_TOKENS) tmax = CHUNK_TOKENS;

    const size_t v_off = (size_t)HKV * PS * D;   // floats
    const int full_pages = tmax >> 4;            // 15 or 16 for this shape

    const uint32_t sbase = (uint32_t)__cvta_generic_to_shared(stagebuf);
    const int tid16 = tid * 16;

    // cooperative page load: 128 threads x 8 cp.async x 16B = 16KB
    auto load_page = [&](int page, int stage) {
        const char* kb = (const char*)(kvc + ((size_t)page * (2 * HKV) + h) * (PS * D));
        const char* vb = (const char*)(kvc + ((size_t)page * (2 * HKV) + h) * (PS * D) + v_off);
        const uint32_t sK = sbase + stage * PAGE_BYTES + tid16;
#pragma unroll
        for (int ps = 0; ps < 4; ps++) {
            cpasync16(sK + ps * 2048,         kb + ps * 2048 + tid16);
            cpasync16(sK + KHALF + ps * 2048, vb + ps * 2048 + tid16);
        }
    };

    // prologue: fill both stages
#pragma unroll
    for (int s = 0; s < NSTAGE; s++) {
        if (s < full_pages) load_page(pages[s], s);
        cp_commit();
    }

    for (int pg = 0; pg < full_pages; pg++) {
        cp_wait<1>();            // page pg's stage resident (1 newer group pending)
        __syncthreads();
        const char* stK = stagebuf + (pg & 1) * PAGE_BYTES;
#pragma unroll
        for (int i = 0; i < 4; i++) {
            const int t512 = (w + i * 4) * 512;
            const float4 k4 = *(const float4*)(stK + t512 + lane4 * 4);
            const float4 v4 = *(const float4*)(stK + KHALF + t512 + lane4 * 4);
            proc_token(st, k4, v4, bit0, bit1);
        }
        __syncthreads();         // all warps done reading before overwrite
        const int nx = pg + NSTAGE;
        if (nx < full_pages) load_page(pages[nx], pg & 1);
        cp_commit();             // always commit (empty groups keep accounting)
    }
    cp_wait<0>();

    // tail: partial last page, direct loads (no smem)
    for (int t = full_pages * PS + w; t < tmax; t += 4) {
        const float* base = kvc
            + ((size_t)pages[t >> 4] * (2 * HKV) + h) * (PS * D)
            + (size_t)(t & (PS - 1)) * D + lane4;
        proc_token(st, ldcs4(base), ldcs4(base + v_off), bit0, bit1);
    }
    __syncthreads();             // before aliasing stagebuf as reduction scratch

    // epilogue scratch aliased onto the (now idle) pipeline buffer
    float (*sm_acc)[G][D] = reinterpret_cast<float (*)[G][D]>(stagebuf);

    // publish per-warp partials, un-permuting heads via computed smem addresses
    const int r = lane & 3;
    if (lane < 4) sm_l[w][perm2(lane)] = st.l_own;   // lane<4 -> r==lane
#pragma unroll
    for (int i = 0; i < G; i++) {
        const int head = perm2(r ^ i);               // head held in slot i
        float4 a = make_float4(st.acc_lo[i].x, st.acc_lo[i].y,
                               st.acc_hi[i].x, st.acc_hi[i].y);
        *(float4*)&sm_acc[w][head][lane4] = a;
    }
    __syncthreads();

    // intra-CTA merge; thread -> (g = tid>>5, dims 4*(tid&31))
    const int cg  = tid >> 5;
    const int cln = tid & 31;
    {
        float L = 0.f;
        float4 a = make_float4(0.f, 0.f, 0.f, 0.f);
#pragma unroll
        for (int wi = 0; wi < 4; wi++) {
            L += sm_l[wi][cg];
            const float4 av = *(const float4*)&sm_acc[wi][cg][cln * 4];
            a.x += av.x; a.y += av.y; a.z += av.z; a.w += av.w;
        }
        const size_t pidx = (((size_t)(b * HKV + h) * CHUNKS + chunk) * G + cg);
        if (cln == 0) g_pl[pidx] = L;
        *(float4*)&g_pa[pidx * D + cln * 4] = a;
    }

    // ---- last-CTA-per-(b,h) merges the CHUNKS chunk partials ----
    __threadfence();
    if (tid == 0)
        sm_arrive = atomicAdd(&g_cnt[b * HKV + h], 1);
    __syncthreads();
    if (sm_arrive != CHUNKS - 1) return;
    __threadfence();   // order partial reads after the counter observation

    const size_t base = ((size_t)(b * HKV + h) * CHUNKS) * G + cg;
    float L = 0.f;
    float4 a = make_float4(0.f, 0.f, 0.f, 0.f);
#pragma unroll
    for (int c = 0; c < CHUNKS; c++) {
        const size_t pidx = base + (size_t)c * G;
        L += __ldcg(&g_pl[pidx]);
        const float4 av = ldcg4(&g_pa[pidx * D + cln * 4]);
        a.x += av.x; a.y += av.y; a.z += av.z; a.w += av.w;
    }
    const float inv = 1.f / L;
    float4 o = make_float4(a.x * inv, a.y * inv, a.z * inv, a.w * inv);
    *(float4*)&out[((size_t)(b * HKV * G) + h * G + cg) * D + cln * 4] = o;

    // reset counter for the next graph replay (only this CTA touches it)
    if (tid == 0) g_cnt[b * HKV + h] = 0;
}

extern "C" void kernel_launch(void* const* d_in, const int* in_sizes, int n_in,
                              void* d_out, int out_size)
{
    const float* q       = (const float*)d_in[0];
    const float* kvc     = (const float*)d_in[1];
    const int*   indptr  = (const int*)d_in[2];
    const int*   indices = (const int*)d_in[3];
    const int*   lastlen = (const int*)d_in[4];
    float* out = (float*)d_out;

    dim3 g1(CHUNKS, HKV, BQ);
    attn_fused<<<g1, 128>>>(q, kvc, indptr, indices, lastlen, out);
}